// round 2
// baseline (speedup 1.0000x reference)
#include <cuda_runtime.h>
#include <math.h>

#define NSTATE 4096
#define LOUT   2048
#define NFFT   4096
#define NCHUNK 64
#define CLEN   64

struct Consts {
    double Q[2][2], Ux[2][2], Uo[2], Uu[2];
    double Ao[2][2], Bo[2], Do[2], Eo;
    double W0[2][2];  // ZGx @ Ux
    double RG;
};
__device__ Consts g_C;
__device__ double g_coef[4096][5];  // n0, n1, n2, tr, det per batch

// ---------------------------------------------------------------------------
// Setup: compute batch-independent circuit matrices from the alpha params.
// ---------------------------------------------------------------------------
__global__ void setup_kernel(const float* a_rg, const float* a_r1,
                             const float* a_c1, const float* a_c2) {
    const double T = 1.0 / 44100.0;
    // sigmoid in fp32 (matches reference), rest in fp64
    double sRG = (double)(1.f / (1.f + expf(-a_rg[0])));
    double sR1 = (double)(1.f / (1.f + expf(-a_r1[0])));
    double sC1 = (double)(1.f / (1.f + expf(-a_c1[0])));
    double sC2 = (double)(1.f / (1.f + expf(-a_c2[0])));
    double RG = (0.9 + 0.2 * sRG) * 1.0e6;
    double R1 = (0.99 + 0.02 * sR1) * 4.7e5;
    double C1 = (0.9 + 0.2 * sC1) * 3.3e-9;
    double C2 = (0.9 + 0.2 * sC2) * 1.0e-9;
    double Gr  = 1.0 / R1;
    double gx1 = 2.0 * C1 / T;
    double gx2 = 2.0 * C2 / T;

    // So = [[Nx^T Gx Nx + Nr^T Gr Nr, Nu^T], [Nu, 0]]
    double M[4][8];
    double So[4][4] = {
        { gx1,      -gx1,       0.0, 1.0},
        {-gx1,  gx1 + Gr,       0.0, 0.0},
        { 0.0,       0.0,       gx2, 0.0},
        { 1.0,       0.0,       0.0, 0.0}};
    for (int i = 0; i < 4; i++)
        for (int j = 0; j < 8; j++)
            M[i][j] = (j < 4) ? So[i][j] : ((j - 4 == i) ? 1.0 : 0.0);
    // Gauss-Jordan with partial pivot
    for (int col = 0; col < 4; col++) {
        int piv = col;
        for (int r = col + 1; r < 4; r++)
            if (fabs(M[r][col]) > fabs(M[piv][col])) piv = r;
        if (piv != col)
            for (int j = 0; j < 8; j++) { double t = M[col][j]; M[col][j] = M[piv][j]; M[piv][j] = t; }
        double inv = 1.0 / M[col][col];
        for (int j = 0; j < 8; j++) M[col][j] *= inv;
        for (int r = 0; r < 4; r++) {
            if (r == col) continue;
            double f = M[r][col];
            for (int j = 0; j < 8; j++) M[r][j] -= f * M[col][j];
        }
    }
    double Si[4][4];
    for (int i = 0; i < 4; i++)
        for (int j = 0; j < 4; j++) Si[i][j] = M[i][j + 4];

    // padded incidence rows (length 4)
    double vr[2][4] = {{0, 1, -1, 0}, {0, 0, 1, 0}};   // Nvp
    double xr[2][4] = {{1, -1, 0, 0}, {0, 0, 1, 0}};   // Nxp
    double orow[4]  = {0, 0, 1, 0};                    // Nop
    // Nup = e3

    auto qf = [&](const double* a, const double* b) {
        double s = 0.0;
        for (int i = 0; i < 4; i++)
            for (int j = 0; j < 4; j++) s += a[i] * Si[i][j] * b[j];
        return s;
    };
    Consts C;
    double gx[2] = {gx1, gx2};
    for (int i = 0; i < 2; i++)
        for (int j = 0; j < 2; j++) {
            C.Q[i][j]  = qf(vr[i], vr[j]);
            C.Ux[i][j] = qf(xr[i], vr[j]);
            double X   = qf(xr[i], xr[j]);
            C.Ao[i][j] = 2.0 * gx[i] * X - (i == j ? 1.0 : 0.0);
        }
    for (int j = 0; j < 2; j++) {
        C.Uo[j] = qf(orow, vr[j]);
        double uu = 0.0;
        for (int k = 0; k < 4; k++) uu += Si[3][k] * vr[j][k];
        C.Uu[j] = uu;
        C.Do[j] = qf(orow, xr[j]);
    }
    for (int i = 0; i < 2; i++) {
        double bi = 0.0;
        for (int k = 0; k < 4; k++) bi += xr[i][k] * Si[k][3];
        C.Bo[i] = 2.0 * gx[i] * bi;
        for (int j = 0; j < 2; j++) C.W0[i][j] = 2.0 * gx[i] * C.Ux[i][j];
    }
    C.Eo = Si[2][3];
    C.RG = RG;
    g_C = C;
}

// ---------------------------------------------------------------------------
// Per-batch biquad coefficients: n0, n1, n2 (num z^2,z,1) and tr, det (den).
// ---------------------------------------------------------------------------
__global__ void coeff_kernel(const float* __restrict__ cond,
                             const float* __restrict__ cw,
                             const float* __restrict__ cb, int B) {
    int b = blockIdx.x * blockDim.x + threadIdx.x;
    if (b >= B) return;
    float zf  = cond[b] * cw[0] + cb[0];
    float pot = 1.f / (1.f + expf(-zf));
    float pf  = (powf(10.f, pot) - 1.f) / 9.f;
    pf = fminf(fmaxf(pf, 1e-4f), 1.f - 1e-4f);
    double p = (double)pf;

    const Consts C = g_C;
    double d0 = (1.0 - p) * C.RG, d1 = p * C.RG;
    double r00 = d0 + C.Q[0][0], r01 = C.Q[0][1];
    double r10 = C.Q[1][0],      r11 = d1 + C.Q[1][1];
    double id  = 1.0 / (r00 * r11 - r01 * r10);
    double S00 = r11 * id, S01 = -r01 * id, S10 = -r10 * id, S11 = r00 * id;

    double W[2][2];
    for (int i = 0; i < 2; i++) {
        W[i][0] = C.W0[i][0] * S00 + C.W0[i][1] * S10;
        W[i][1] = C.W0[i][0] * S01 + C.W0[i][1] * S11;
    }
    double A[2][2], Bm[2];
    for (int i = 0; i < 2; i++) {
        for (int j = 0; j < 2; j++)
            A[i][j] = C.Ao[i][j] - (W[i][0] * C.Ux[j][0] + W[i][1] * C.Ux[j][1]);
        Bm[i] = C.Bo[i] - (W[i][0] * C.Uu[0] + W[i][1] * C.Uu[1]);
    }
    double V0 = C.Uo[0] * S00 + C.Uo[1] * S10;
    double V1 = C.Uo[0] * S01 + C.Uo[1] * S11;
    double Dm[2];
    for (int j = 0; j < 2; j++)
        Dm[j] = C.Do[j] - (V0 * C.Ux[j][0] + V1 * C.Ux[j][1]);
    double Em = C.Eo - (V0 * C.Uu[0] + V1 * C.Uu[1]);

    double tr  = A[0][0] + A[1][1];
    double det = A[0][0] * A[1][1] - A[0][1] * A[1][0];
    double E00 = A[0][0] - Bm[0] * Dm[0], E01 = A[0][1] - Bm[0] * Dm[1];
    double E10 = A[1][0] - Bm[1] * Dm[0], E11 = A[1][1] - Bm[1] * Dm[1];
    double trE = E00 + E11, detE = E00 * E11 - E01 * E10;

    g_coef[b][0] = Em;                           // n0 (coef of z^2)
    g_coef[b][1] = -trE - (Em - 1.0) * tr;       // n1
    g_coef[b][2] = detE + (Em - 1.0) * det;      // n2
    g_coef[b][3] = tr;
    g_coef[b][4] = det;
}

// ---------------------------------------------------------------------------
// Circular backward biquad via chunk-affine decomposition (exact periodic).
// st[0:2048) = state[b, 2048:4096); st[2048:4096) = x[b, 0:2048).
// y[n] = s[n] + tr*y[n+1] - det*y[n+2],  s[n] = n0*st[n] + n1*st[n+1] + n2*st[n+2]
// out[b, i] = y[2048 + i].
// ---------------------------------------------------------------------------
__global__ void __launch_bounds__(256, 1)
filter_kernel(const float* __restrict__ x, const float* __restrict__ state,
              float* __restrict__ out, int B) {
    __shared__ double s_s[NFFT + NCHUNK];        // padded: idx = n + (n>>6)
    __shared__ float  yout[LOUT + LOUT / CLEN];  // padded: idx = i + (i>>6)
    __shared__ double Mv[NCHUNK][4];
    __shared__ double Pv[NCHUNK][2];
    __shared__ double vin[NCHUNK][2];

    int b   = blockIdx.x;
    int tid = threadIdx.x;
    double n0 = g_coef[b][0], n1 = g_coef[b][1], n2 = g_coef[b][2];
    double tr = g_coef[b][3], dt = g_coef[b][4];

    const float* stt = state + (size_t)b * NSTATE + LOUT;  // state tail
    const float* xb  = x + (size_t)b * LOUT;

    // Phase A: source term s[n] into padded shared
    for (int n = tid; n < NFFT; n += 256) {
        int i1 = (n + 1) & (NFFT - 1), i2 = (n + 2) & (NFFT - 1);
        double v0 = (n  < LOUT) ? (double)stt[n]  : (double)xb[n - LOUT];
        double v1 = (i1 < LOUT) ? (double)stt[i1] : (double)xb[i1 - LOUT];
        double v2 = (i2 < LOUT) ? (double)stt[i2] : (double)xb[i2 - LOUT];
        s_s[n + (n >> 6)] = n0 * v0 + n1 * v1 + n2 * v2;
    }
    __syncthreads();

    // Phase B: per-chunk affine map (M = T^64, P = particular solution)
    if (tid < NCHUNK) {
        int c = tid;
        int n = NFFT - 1 - CLEN * c;
        double pa = 0.0, pb = 0.0;
        double ma0 = 1.0, ma1 = 0.0, mb0 = 0.0, mb1 = 1.0;
#pragma unroll 4
        for (int i = 0; i < CLEN; i++, n--) {
            double s  = s_s[n + (n >> 6)];
            double pc = fma(tr, pa, fma(-dt, pb, s));
            double m0 = fma(tr, ma0, -dt * mb0);
            double m1 = fma(tr, ma1, -dt * mb1);
            pb = pa; pa = pc;
            mb0 = ma0; mb1 = ma1; ma0 = m0; ma1 = m1;
        }
        Mv[c][0] = ma0; Mv[c][1] = ma1; Mv[c][2] = mb0; Mv[c][3] = mb1;
        Pv[c][0] = pa;  Pv[c][1] = pb;
    }
    __syncthreads();

    // Phase C: sequential composition + periodic fixed point (thread 0)
    if (tid == 0) {
        double F00 = 1, F01 = 0, F10 = 0, F11 = 1, P0 = 0, P1 = 0;
        for (int c = 0; c < NCHUNK; c++) {
            double m00 = Mv[c][0], m01 = Mv[c][1], m10 = Mv[c][2], m11 = Mv[c][3];
            double q0 = Pv[c][0], q1 = Pv[c][1];
            double np0 = m00 * P0 + m01 * P1 + q0;
            double np1 = m10 * P0 + m11 * P1 + q1;
            double f00 = m00 * F00 + m01 * F10, f01 = m00 * F01 + m01 * F11;
            double f10 = m10 * F00 + m11 * F10, f11 = m10 * F01 + m11 * F11;
            P0 = np0; P1 = np1; F00 = f00; F01 = f01; F10 = f10; F11 = f11;
        }
        // periodic BC: v = F v + P  ->  (I - F) v = P
        double a = 1.0 - F00, bb = -F01, cc = -F10, dd = 1.0 - F11;
        double idn = 1.0 / (a * dd - bb * cc);
        double v0 = (dd * P0 - bb * P1) * idn;
        double v1 = (-cc * P0 + a * P1) * idn;
        vin[0][0] = v0; vin[0][1] = v1;
        for (int c = 1; c < NCHUNK; c++) {
            double w0 = Mv[c - 1][0] * v0 + Mv[c - 1][1] * v1 + Pv[c - 1][0];
            double w1 = Mv[c - 1][2] * v0 + Mv[c - 1][3] * v1 + Pv[c - 1][1];
            vin[c][0] = w0; vin[c][1] = w1;
            v0 = w0; v1 = w1;
        }
    }
    __syncthreads();

    // Phase D: replay the 32 chunks covering n in [2048, 4096) with exact ICs
    if (tid < 32) {
        int c = tid;
        int n = NFFT - 1 - CLEN * c;
        double pa = vin[c][0], pb = vin[c][1];
#pragma unroll 4
        for (int i = 0; i < CLEN; i++, n--) {
            double s  = s_s[n + (n >> 6)];
            double yc = fma(tr, pa, fma(-dt, pb, s));
            int k = n - LOUT;
            yout[k + (k >> 6)] = (float)yc;
            pb = pa; pa = yc;
        }
    }
    __syncthreads();

    // Phase E: coalesced writeback
    float* ob = out + (size_t)b * LOUT;
    for (int i = tid; i < LOUT; i += 256) ob[i] = yout[i + (i >> 6)];
}

extern "C" void kernel_launch(void* const* d_in, const int* in_sizes, int n_in,
                              void* d_out, int out_size) {
    const float* x     = (const float*)d_in[0];
    const float* cond  = (const float*)d_in[1];
    const float* state = (const float*)d_in[2];
    const float* a_rg  = (const float*)d_in[3];
    const float* a_r1  = (const float*)d_in[4];
    const float* a_c1  = (const float*)d_in[5];
    const float* a_c2  = (const float*)d_in[6];
    const float* cw    = (const float*)d_in[7];
    const float* cb    = (const float*)d_in[8];

    int B = in_sizes[1];  // cond is [B, 1]
    if (B > 4096) B = 4096;

    setup_kernel<<<1, 1>>>(a_rg, a_r1, a_c1, a_c2);
    coeff_kernel<<<(B + 255) / 256, 256>>>(cond, cw, cb, B);
    filter_kernel<<<B, 256>>>(x, state, (float*)d_out, B);
}

// round 3
// speedup vs baseline: 8.1836x; 8.1836x over previous
#include <cuda_runtime.h>
#include <math.h>

#define LOUT 2048
#define NFFT 4096
#define CLEN 32
#define NCH  128
#define TPB  128

// per batch: n0, n1, n2, tr, det (stride 8 floats)
__device__ float g_coef[4096 * 8];

// ---------------------------------------------------------------------------
// Coefficient kernel: closed-form circuit solve (no 4x4 Gauss-Jordan needed).
// So = [[g1,-g1,0,1],[-g1,g1+Gr,0,0],[0,0,g2,0],[1,0,0,0]] has closed inverse:
//   v1=r4; v2=(r2+g1 r4)/(g1+Gr); v3=r3/g2; iu=r1+g1 v2-g1 r4.
// All quadratic forms reduce to a handful of scalars.
// ---------------------------------------------------------------------------
__global__ void coeff_kernel(const float* __restrict__ cond,
                             const float* __restrict__ cw,
                             const float* __restrict__ cb,
                             const float* __restrict__ a_rg,
                             const float* __restrict__ a_r1,
                             const float* __restrict__ a_c1,
                             const float* __restrict__ a_c2, int B) {
    int b = blockIdx.x * blockDim.x + threadIdx.x;
    if (b >= B) return;

    const double T = 1.0 / 44100.0;
    double sRG = (double)(1.f / (1.f + expf(-a_rg[0])));
    double sR1 = (double)(1.f / (1.f + expf(-a_r1[0])));
    double sC1 = (double)(1.f / (1.f + expf(-a_c1[0])));
    double sC2 = (double)(1.f / (1.f + expf(-a_c2[0])));
    double RG = (0.9 + 0.2 * sRG) * 1.0e6;
    double R1 = (0.99 + 0.02 * sR1) * 4.7e5;
    double C1 = (0.9 + 0.2 * sC1) * 3.3e-9;
    double C2 = (0.9 + 0.2 * sC2) * 1.0e-9;
    double Gr = 1.0 / R1, g1 = 2.0 * C1 / T, g2 = 2.0 * C2 / T;
    double G = g1 + Gr, h = g1 / G, iG = 1.0 / G, ig2 = 1.0 / g2;

    // closed-form reduced matrices
    double Q00 = iG + ig2, Q01 = -ig2, Q11 = ig2;
    double Ux00 = -iG, Ux01 = 0.0, Ux10 = -ig2, Ux11 = ig2;
    double Ao00 = 2.0 * g1 * iG - 1.0, Ao11 = 1.0;   // off-diags are 0
    double Uo0 = -ig2, Uo1 = ig2;
    double Uu0 = h;                                   // Uu1 = 0
    double Do1 = ig2;                                 // Do0 = 0
    double Bo0 = 2.0 * g1 * (1.0 - h);                // Bo1 = 0
    double W000 = -2.0 * g1 * iG;                     // W0 = 2*Gx*Ux
    double W010 = -2.0, W011 = 2.0;                   // W001 = 0
    // Eo = 0

    // pot taper (fp32, matching reference)
    float zf  = cond[b] * cw[0] + cb[0];
    float pot = 1.f / (1.f + expf(-zf));
    float pf  = (powf(10.f, pot) - 1.f) / 9.f;
    pf = fminf(fmaxf(pf, 1e-4f), 1.f - 1e-4f);
    double p = (double)pf;

    double r00 = (1.0 - p) * RG + Q00, r01 = Q01, r11 = p * RG + Q11;
    double id  = 1.0 / (r00 * r11 - r01 * r01);
    double S00 = r11 * id, S01 = -r01 * id, S11 = r00 * id;  // symmetric

    double W00 = W000 * S00;
    double W01 = W000 * S01;
    double W10 = W010 * S00 + W011 * S01;
    double W11 = W010 * S01 + W011 * S11;

    double A00 = Ao00 - (W00 * Ux00 + W01 * Ux01);
    double A01 =       - (W00 * Ux10 + W01 * Ux11);
    double A10 =       - (W10 * Ux00 + W11 * Ux01);
    double A11 = Ao11 - (W10 * Ux10 + W11 * Ux11);
    double Bm0 = Bo0 - W00 * Uu0;
    double Bm1 =     - W10 * Uu0;
    double V0  = Uo0 * S00 + Uo1 * S01;
    double V1  = Uo0 * S01 + Uo1 * S11;
    double Dm0 =       - (V0 * Ux00 + V1 * Ux01);
    double Dm1 = Do1   - (V0 * Ux10 + V1 * Ux11);
    double Em  = -(V0 * Uu0);

    double tr  = A00 + A11;
    double det = A00 * A11 - A01 * A10;
    double E00 = A00 - Bm0 * Dm0, E01 = A01 - Bm0 * Dm1;
    double E10 = A10 - Bm1 * Dm0, E11 = A11 - Bm1 * Dm1;
    double trE = E00 + E11, detE = E00 * E11 - E01 * E10;

    float* cf = g_coef + b * 8;
    cf[0] = (float)Em;
    cf[1] = (float)(-trE - (Em - 1.0) * tr);
    cf[2] = (float)(detE + (Em - 1.0) * det);
    cf[3] = (float)tr;
    cf[4] = (float)det;
}

// ---------------------------------------------------------------------------
// Filter kernel: exact circular backward biquad via 128-chunk affine scan.
//   y[n] = s[n] + tr*y[n+1] - det*y[n+2],   s[n] = n0*st[n]+n1*st[n+1]+n2*st[n+2]
// One block per batch, 128 threads, 32 steps/thread; fully parallel output fix.
// ---------------------------------------------------------------------------
#define IDX5(n) ((n) + ((n) >> 5))

__global__ void __launch_bounds__(TPB)
filter_kernel(const float* __restrict__ x, const float* __restrict__ state,
              float* __restrict__ out) {
    __shared__ float st[4226];                 // IDX5(4097)=4225
    __shared__ float pA[2112], m0A[2112], m1A[2112];
    __shared__ float scanArr[NCH][6];
    __shared__ float warpTot[4][6];
    __shared__ float2 vin[64];

    int b = blockIdx.x, tid = threadIdx.x;
    const float* cf = g_coef + b * 8;
    float n0 = cf[0], n1 = cf[1], n2 = cf[2], tr = cf[3], dt = cf[4];

    const float* stt = state + (size_t)b * NFFT + LOUT;  // state tail (last 2048)
    const float* xb  = x + (size_t)b * LOUT;

    // load periodic buffer: [0,2048)=state tail, [2048,4096)=x, +2 wrap copies
    for (int n = tid; n < NFFT; n += TPB) {
        float v = (n < LOUT) ? stt[n] : xb[n - LOUT];
        st[IDX5(n)] = v;
    }
    if (tid < 2) st[IDX5(NFFT + tid)] = stt[tid];
    __syncthreads();

    // Pass 1: chunk c = tid runs 32 backward steps with zero IC, tracking the
    // affine map (M = running T^i first row, P = zero-IC solution).
    int c = tid;
    int n = NFFT - 1 - CLEN * c;
    float v1 = st[IDX5(n + 1)], v2 = st[IDX5(n + 2)];
    float pa = 0.f, pb = 0.f;
    float ma0 = 1.f, ma1 = 0.f, mb0 = 0.f, mb1 = 1.f;
    const bool storeCh = (c < 64);
#pragma unroll
    for (int i = 0; i < CLEN; i++) {
        float v0 = st[IDX5(n)];
        float s  = fmaf(n0, v0, fmaf(n1, v1, n2 * v2));
        float pc = fmaf(tr, pa, fmaf(-dt, pb, s));
        float t0 = fmaf(tr, ma0, -dt * mb0);
        float t1 = fmaf(tr, ma1, -dt * mb1);
        mb0 = ma0; mb1 = ma1; ma0 = t0; ma1 = t1;
        pb = pa; pa = pc;
        if (storeCh) {
            int k = n - LOUT, ki = IDX5(k);
            pA[ki] = pc; m0A[ki] = t0; m1A[ki] = t1;
        }
        v2 = v1; v1 = v0; n--;
    }
    // now (ma,mb,pa,pb) = this chunk's (M, P):  v_out = M v_in + P

    // Intra-warp inclusive affine scan (chunk order = increasing tid).
    // compose: self ∘ left  ->  M = M_s M_l ; P = M_s P_l + P_s
    const unsigned fullm = 0xffffffffu;
    int lane = tid & 31;
#pragma unroll
    for (int d = 1; d < 32; d <<= 1) {
        float la0 = __shfl_up_sync(fullm, ma0, d);
        float la1 = __shfl_up_sync(fullm, ma1, d);
        float lb0 = __shfl_up_sync(fullm, mb0, d);
        float lb1 = __shfl_up_sync(fullm, mb1, d);
        float lp0 = __shfl_up_sync(fullm, pa, d);
        float lp1 = __shfl_up_sync(fullm, pb, d);
        if (lane >= d) {
            float na0 = ma0 * la0 + ma1 * lb0;
            float na1 = ma0 * la1 + ma1 * lb1;
            float nb0 = mb0 * la0 + mb1 * lb0;
            float nb1 = mb0 * la1 + mb1 * lb1;
            float np0 = ma0 * lp0 + ma1 * lp1 + pa;
            float np1 = mb0 * lp0 + mb1 * lp1 + pb;
            ma0 = na0; ma1 = na1; mb0 = nb0; mb1 = nb1; pa = np0; pb = np1;
        }
    }
    int w = tid >> 5;
    if (lane == 31) {
        warpTot[w][0] = ma0; warpTot[w][1] = ma1;
        warpTot[w][2] = mb0; warpTot[w][3] = mb1;
        warpTot[w][4] = pa;  warpTot[w][5] = pb;
    }
    __syncthreads();

    // cross-warp: compose preceding warp totals (applied first), then self.
    if (w > 0) {
        float LA0 = warpTot[0][0], LA1 = warpTot[0][1];
        float LB0 = warpTot[0][2], LB1 = warpTot[0][3];
        float LP0 = warpTot[0][4], LP1 = warpTot[0][5];
        for (int ww = 1; ww < w; ww++) {
            float t0 = warpTot[ww][0], t1 = warpTot[ww][1];
            float t2 = warpTot[ww][2], t3 = warpTot[ww][3];
            float t4 = warpTot[ww][4], t5 = warpTot[ww][5];
            float nA0 = t0 * LA0 + t1 * LB0, nA1 = t0 * LA1 + t1 * LB1;
            float nB0 = t2 * LA0 + t3 * LB0, nB1 = t2 * LA1 + t3 * LB1;
            float nP0 = t0 * LP0 + t1 * LP1 + t4;
            float nP1 = t2 * LP0 + t3 * LP1 + t5;
            LA0 = nA0; LA1 = nA1; LB0 = nB0; LB1 = nB1; LP0 = nP0; LP1 = nP1;
        }
        float na0 = ma0 * LA0 + ma1 * LB0;
        float na1 = ma0 * LA1 + ma1 * LB1;
        float nb0 = mb0 * LA0 + mb1 * LB0;
        float nb1 = mb0 * LA1 + mb1 * LB1;
        float np0 = ma0 * LP0 + ma1 * LP1 + pa;
        float np1 = mb0 * LP0 + mb1 * LP1 + pb;
        ma0 = na0; ma1 = na1; mb0 = nb0; mb1 = nb1; pa = np0; pb = np1;
    }
    scanArr[c][0] = ma0; scanArr[c][1] = ma1;
    scanArr[c][2] = mb0; scanArr[c][3] = mb1;
    scanArr[c][4] = pa;  scanArr[c][5] = pb;
    __syncthreads();

    // periodic fixed point v = F v + P  ->  v = (I-F)^{-1} P  (F = T^4096 ~ 0)
    float F00 = scanArr[NCH - 1][0], F01 = scanArr[NCH - 1][1];
    float F10 = scanArr[NCH - 1][2], F11 = scanArr[NCH - 1][3];
    float Pt0 = scanArr[NCH - 1][4], Pt1 = scanArr[NCH - 1][5];
    float aa = 1.f - F00, bb = -F01, cc = -F10, dd = 1.f - F11;
    float inv = 1.f / (aa * dd - bb * cc);
    float w0 = (dd * Pt0 - bb * Pt1) * inv;
    float w1 = (-cc * Pt0 + aa * Pt1) * inv;

    if (c < 64) {
        float vx, vy;
        if (c == 0) { vx = w0; vy = w1; }
        else {
            float e0 = scanArr[c - 1][0], e1 = scanArr[c - 1][1];
            float e2 = scanArr[c - 1][2], e3 = scanArr[c - 1][3];
            float e4 = scanArr[c - 1][4], e5 = scanArr[c - 1][5];
            vx = e0 * w0 + e1 * w1 + e4;
            vy = e2 * w0 + e3 * w1 + e5;
        }
        vin[c] = make_float2(vx, vy);
    }
    __syncthreads();

    // Output: y[2048+k] = p + m0*vin.x + m1*vin.y, fully parallel.
    float* ob = out + (size_t)b * LOUT;
    for (int k = tid; k < LOUT; k += TPB) {
        int cc2 = (LOUT - 1 - k) >> 5;
        int ki  = IDX5(k);
        float2 v = vin[cc2];
        float y = fmaf(m0A[ki], v.x, fmaf(m1A[ki], v.y, pA[ki]));
        ob[k] = y;
    }
}

extern "C" void kernel_launch(void* const* d_in, const int* in_sizes, int n_in,
                              void* d_out, int out_size) {
    const float* x     = (const float*)d_in[0];
    const float* cond  = (const float*)d_in[1];
    const float* state = (const float*)d_in[2];
    const float* a_rg  = (const float*)d_in[3];
    const float* a_r1  = (const float*)d_in[4];
    const float* a_c1  = (const float*)d_in[5];
    const float* a_c2  = (const float*)d_in[6];
    const float* cw    = (const float*)d_in[7];
    const float* cb    = (const float*)d_in[8];

    int B = in_sizes[1];  // cond is [B,1]
    if (B > 4096) B = 4096;

    coeff_kernel<<<(B + 127) / 128, 128>>>(cond, cw, cb, a_rg, a_r1, a_c1, a_c2, B);
    filter_kernel<<<B, TPB>>>(x, state, (float*)d_out);
}

// round 5
// speedup vs baseline: 20.2779x; 2.4779x over previous
#include <cuda_runtime.h>
#include <math.h>

#define LOUT 2048
#define NFFT 4096
#define CLEN 32
#define NCH  128
#define TPB  128

// per batch: n0, n1, n2, tr, det (stride 8 floats)
__device__ float g_coef[4096 * 8];

// ---------------------------------------------------------------------------
// Coefficient kernel: closed-form circuit solve (fp64, tiny).
// ---------------------------------------------------------------------------
__global__ void coeff_kernel(const float* __restrict__ cond,
                             const float* __restrict__ cw,
                             const float* __restrict__ cb,
                             const float* __restrict__ a_rg,
                             const float* __restrict__ a_r1,
                             const float* __restrict__ a_c1,
                             const float* __restrict__ a_c2, int B) {
    int b = blockIdx.x * blockDim.x + threadIdx.x;
    if (b >= B) return;

    const double T = 1.0 / 44100.0;
    double sRG = (double)(1.f / (1.f + expf(-a_rg[0])));
    double sR1 = (double)(1.f / (1.f + expf(-a_r1[0])));
    double sC1 = (double)(1.f / (1.f + expf(-a_c1[0])));
    double sC2 = (double)(1.f / (1.f + expf(-a_c2[0])));
    double RG = (0.9 + 0.2 * sRG) * 1.0e6;
    double R1 = (0.99 + 0.02 * sR1) * 4.7e5;
    double C1 = (0.9 + 0.2 * sC1) * 3.3e-9;
    double C2 = (0.9 + 0.2 * sC2) * 1.0e-9;
    double Gr = 1.0 / R1, g1 = 2.0 * C1 / T, g2 = 2.0 * C2 / T;
    double G = g1 + Gr, h = g1 / G, iG = 1.0 / G, ig2 = 1.0 / g2;

    double Q00 = iG + ig2, Q01 = -ig2, Q11 = ig2;
    double Ux00 = -iG, Ux01 = 0.0, Ux10 = -ig2, Ux11 = ig2;
    double Ao00 = 2.0 * g1 * iG - 1.0, Ao11 = 1.0;
    double Uo0 = -ig2, Uo1 = ig2;
    double Uu0 = h;
    double Do1 = ig2;
    double Bo0 = 2.0 * g1 * (1.0 - h);
    double W000 = -2.0 * g1 * iG;
    double W010 = -2.0, W011 = 2.0;

    float zf  = cond[b] * cw[0] + cb[0];
    float pot = 1.f / (1.f + expf(-zf));
    float pf  = (powf(10.f, pot) - 1.f) / 9.f;
    pf = fminf(fmaxf(pf, 1e-4f), 1.f - 1e-4f);
    double p = (double)pf;

    double r00 = (1.0 - p) * RG + Q00, r01 = Q01, r11 = p * RG + Q11;
    double id  = 1.0 / (r00 * r11 - r01 * r01);
    double S00 = r11 * id, S01 = -r01 * id, S11 = r00 * id;

    double W00 = W000 * S00;
    double W01 = W000 * S01;
    double W10 = W010 * S00 + W011 * S01;
    double W11 = W010 * S01 + W011 * S11;

    double A00 = Ao00 - (W00 * Ux00 + W01 * Ux01);
    double A01 =       - (W00 * Ux10 + W01 * Ux11);
    double A10 =       - (W10 * Ux00 + W11 * Ux01);
    double A11 = Ao11 - (W10 * Ux10 + W11 * Ux11);
    double Bm0 = Bo0 - W00 * Uu0;
    double Bm1 =     - W10 * Uu0;
    double V0  = Uo0 * S00 + Uo1 * S01;
    double V1  = Uo0 * S01 + Uo1 * S11;
    double Dm0 =       - (V0 * Ux00 + V1 * Ux01);
    double Dm1 = Do1   - (V0 * Ux10 + V1 * Ux11);
    double Em  = -(V0 * Uu0);

    double tr  = A00 + A11;
    double det = A00 * A11 - A01 * A10;
    double E00 = A00 - Bm0 * Dm0, E01 = A01 - Bm0 * Dm1;
    double E10 = A10 - Bm1 * Dm0, E11 = A11 - Bm1 * Dm1;
    double trE = E00 + E11, detE = E00 * E11 - E01 * E10;

    float* cf = g_coef + b * 8;
    cf[0] = (float)Em;
    cf[1] = (float)(-trE - (Em - 1.0) * tr);
    cf[2] = (float)(detE + (Em - 1.0) * det);
    cf[3] = (float)tr;
    cf[4] = (float)det;
}

// ---------------------------------------------------------------------------
// Filter kernel: exact circular backward biquad via 128-chunk affine scan +
// 64-chunk replay. y overlaid into the first half of the st buffer:
//   replay reads padded idx >= IDX5(2048)=2112, writes idx <= IDX5(2047)=2110.
// Global side uses float4 (aligned); shared side is scalar (pad breaks 16B
// alignment of the padded index — that was the R4 trap).
// ---------------------------------------------------------------------------
#define IDX5(n) ((n) + ((n) >> 5))

__global__ void __launch_bounds__(TPB)
filter_kernel(const float* __restrict__ x, const float* __restrict__ state,
              float* __restrict__ out) {
    __shared__ float st[4226];            // IDX5(4097)=4225
    __shared__ float scanArr[NCH][6];
    __shared__ float warpTot[4][6];

    int b = blockIdx.x, tid = threadIdx.x;
    const float* cf = g_coef + b * 8;
    float n0 = cf[0], n1 = cf[1], n2 = cf[2], tr = cf[3], dt = cf[4];

    const float* stt = state + (size_t)b * NFFT + LOUT;  // state tail
    const float* xb  = x + (size_t)b * LOUT;

    // load periodic buffer: LDG.128, scalar STS (padded idx not 16B-aligned)
#pragma unroll
    for (int it = 0; it < 8; it++) {
        int n = (tid + it * TPB) * 4;
        float4 v = (n < LOUT) ? *(const float4*)(stt + n)
                              : *(const float4*)(xb + n - LOUT);
        int i0 = IDX5(n);                 // n..n+3 stay in one pad group
        st[i0] = v.x; st[i0 + 1] = v.y; st[i0 + 2] = v.z; st[i0 + 3] = v.w;
    }
    if (tid < 2) st[IDX5(NFFT + tid)] = stt[tid];
    __syncthreads();

    // Pass 1: chunk c = tid, 32 backward steps, zero IC, track affine map.
    int c = tid;
    int nhi = NFFT - 1 - CLEN * c;        // nhi ≡ 31 (mod 32): chunk in one pad group
    int off = IDX5(nhi);
    float v1 = st[IDX5(nhi + 1)], v2 = st[IDX5(nhi + 2)];
    float pa = 0.f, pb = 0.f;
    float ma0 = 1.f, ma1 = 0.f, mb0 = 0.f, mb1 = 1.f;
#pragma unroll
    for (int i = 0; i < CLEN; i++) {
        float v0 = st[off - i];
        float s  = fmaf(n0, v0, fmaf(n1, v1, n2 * v2));
        float pc = fmaf(tr, pa, fmaf(-dt, pb, s));
        float t0 = fmaf(tr, ma0, -dt * mb0);
        float t1 = fmaf(tr, ma1, -dt * mb1);
        mb0 = ma0; mb1 = ma1; ma0 = t0; ma1 = t1;
        pb = pa; pa = pc;
        v2 = v1; v1 = v0;
    }

    // Intra-warp inclusive affine scan (compose: self ∘ left).
    const unsigned fullm = 0xffffffffu;
    int lane = tid & 31;
#pragma unroll
    for (int d = 1; d < 32; d <<= 1) {
        float la0 = __shfl_up_sync(fullm, ma0, d);
        float la1 = __shfl_up_sync(fullm, ma1, d);
        float lb0 = __shfl_up_sync(fullm, mb0, d);
        float lb1 = __shfl_up_sync(fullm, mb1, d);
        float lp0 = __shfl_up_sync(fullm, pa, d);
        float lp1 = __shfl_up_sync(fullm, pb, d);
        if (lane >= d) {
            float na0 = ma0 * la0 + ma1 * lb0;
            float na1 = ma0 * la1 + ma1 * lb1;
            float nb0 = mb0 * la0 + mb1 * lb0;
            float nb1 = mb0 * la1 + mb1 * lb1;
            float np0 = ma0 * lp0 + ma1 * lp1 + pa;
            float np1 = mb0 * lp0 + mb1 * lp1 + pb;
            ma0 = na0; ma1 = na1; mb0 = nb0; mb1 = nb1; pa = np0; pb = np1;
        }
    }
    int w = tid >> 5;
    if (lane == 31) {
        warpTot[w][0] = ma0; warpTot[w][1] = ma1;
        warpTot[w][2] = mb0; warpTot[w][3] = mb1;
        warpTot[w][4] = pa;  warpTot[w][5] = pb;
    }
    __syncthreads();

    // cross-warp composition
    if (w > 0) {
        float LA0 = warpTot[0][0], LA1 = warpTot[0][1];
        float LB0 = warpTot[0][2], LB1 = warpTot[0][3];
        float LP0 = warpTot[0][4], LP1 = warpTot[0][5];
        for (int ww = 1; ww < w; ww++) {
            float t0 = warpTot[ww][0], t1 = warpTot[ww][1];
            float t2 = warpTot[ww][2], t3 = warpTot[ww][3];
            float t4 = warpTot[ww][4], t5 = warpTot[ww][5];
            float nA0 = t0 * LA0 + t1 * LB0, nA1 = t0 * LA1 + t1 * LB1;
            float nB0 = t2 * LA0 + t3 * LB0, nB1 = t2 * LA1 + t3 * LB1;
            float nP0 = t0 * LP0 + t1 * LP1 + t4;
            float nP1 = t2 * LP0 + t3 * LP1 + t5;
            LA0 = nA0; LA1 = nA1; LB0 = nB0; LB1 = nB1; LP0 = nP0; LP1 = nP1;
        }
        float na0 = ma0 * LA0 + ma1 * LB0;
        float na1 = ma0 * LA1 + ma1 * LB1;
        float nb0 = mb0 * LA0 + mb1 * LB0;
        float nb1 = mb0 * LA1 + mb1 * LB1;
        float np0 = ma0 * LP0 + ma1 * LP1 + pa;
        float np1 = mb0 * LP0 + mb1 * LP1 + pb;
        ma0 = na0; ma1 = na1; mb0 = nb0; mb1 = nb1; pa = np0; pb = np1;
    }
    scanArr[c][0] = ma0; scanArr[c][1] = ma1;
    scanArr[c][2] = mb0; scanArr[c][3] = mb1;
    scanArr[c][4] = pa;  scanArr[c][5] = pb;
    __syncthreads();

    // Replay: threads c<64 solve the periodic fixed point, get exact chunk IC,
    // re-run 32 steps and write y into st[IDX5(0..2047)] (disjoint from reads).
    if (c < 64) {
        float F00 = scanArr[NCH - 1][0], F01 = scanArr[NCH - 1][1];
        float F10 = scanArr[NCH - 1][2], F11 = scanArr[NCH - 1][3];
        float Pt0 = scanArr[NCH - 1][4], Pt1 = scanArr[NCH - 1][5];
        float aa = 1.f - F00, bb = -F01, cc = -F10, dd = 1.f - F11;
        float inv = 1.f / (aa * dd - bb * cc);
        float w0 = (dd * Pt0 - bb * Pt1) * inv;
        float w1 = (-cc * Pt0 + aa * Pt1) * inv;

        float vx, vy;
        if (c == 0) { vx = w0; vy = w1; }
        else {
            float e0 = scanArr[c - 1][0], e1 = scanArr[c - 1][1];
            float e2 = scanArr[c - 1][2], e3 = scanArr[c - 1][3];
            float e4 = scanArr[c - 1][4], e5 = scanArr[c - 1][5];
            vx = e0 * w0 + e1 * w1 + e4;
            vy = e2 * w0 + e3 * w1 + e5;
        }

        int rb  = IDX5(nhi);
        float r1 = st[IDX5(nhi + 1)], r2 = st[IDX5(nhi + 2)];
        float ya = vx, yb = vy;
        int kbase = IDX5(nhi - LOUT);     // same pad group (nhi-2048 ≡ 31 mod 32)
#pragma unroll
        for (int i = 0; i < CLEN; i++) {
            float r0 = st[rb - i];
            float s  = fmaf(n0, r0, fmaf(n1, r1, n2 * r2));
            float yc = fmaf(tr, ya, fmaf(-dt, yb, s));
            st[kbase - i] = yc;
            yb = ya; ya = yc;
            r2 = r1; r1 = r0;
        }
    }
    __syncthreads();

    // writeback: scalar LDS (padded idx), STG.128 (global is aligned)
    float* ob = out + (size_t)b * LOUT;
#pragma unroll
    for (int it = 0; it < 4; it++) {
        int k = (tid + it * TPB) * 4;
        int i0 = IDX5(k);
        float4 v = make_float4(st[i0], st[i0 + 1], st[i0 + 2], st[i0 + 3]);
        *(float4*)(ob + k) = v;
    }
}

extern "C" void kernel_launch(void* const* d_in, const int* in_sizes, int n_in,
                              void* d_out, int out_size) {
    const float* x     = (const float*)d_in[0];
    const float* cond  = (const float*)d_in[1];
    const float* state = (const float*)d_in[2];
    const float* a_rg  = (const float*)d_in[3];
    const float* a_r1  = (const float*)d_in[4];
    const float* a_c1  = (const float*)d_in[5];
    const float* a_c2  = (const float*)d_in[6];
    const float* cw    = (const float*)d_in[7];
    const float* cb    = (const float*)d_in[8];

    int B = in_sizes[1];  // cond is [B,1]
    if (B > 4096) B = 4096;

    coeff_kernel<<<(B + 127) / 128, 128>>>(cond, cw, cb, a_rg, a_r1, a_c1, a_c2, B);
    filter_kernel<<<B, TPB>>>(x, state, (float*)d_out);
}